// round 17
// baseline (speedup 1.0000x reference)
#include <cuda_runtime.h>
#include <cuda_fp16.h>
#include <math.h>

// Problem dims
#define Bq   128
#define Sq   256
#define Eq   512
#define Hq   1024
#define Vq   2048
#define G4H  4096   // 4*H
#define Kout 2048   // 2*H (output GEMM K)
#define Mout (Bq * Sq)

// ---------------------------------------------------------------------------
// Scratch (device globals; no allocation allowed)
// ---------------------------------------------------------------------------
__device__ float g_btf[G4H];
__device__ float g_btb[G4H];
__device__ float g_embWtf[Vq * G4H];         // 32 MB (bias folded)
__device__ float g_embWtb[Vq * G4H];
__device__ float g_c[2][Bq * Hq];            // [dir] cell state (fp32)
__device__ unsigned g_flags[4][32];          // per-(group, ctaX) step flags
__device__ __half g_emb16[Vq * Eq];          // 2 MB: emb in fp16
// W fp16, gate-interleaved, TRANSPOSED: [c=j*4+g][e]
__device__ __half g_Wt16f[G4H * Eq];         // 4 MB
__device__ __half g_Wt16b[G4H * Eq];
// Recurrent weights, plain fp16, gate-interleaved, TRANSPOSED: [n=j*4+g][k]
__device__ __half g_Uhif[G4H * Hq];          // 8 MB
__device__ __half g_Uhib[G4H * Hq];
// hcat fp16; row m = b*S+s, col = dir*H+j.
__device__ __half g_Ahi[(size_t)Mout * Kout]; // 128 MB
// Wd transposed, plain fp16: B[n][k] = Wd[k][n]
__device__ __half g_Bhi[Vq * Kout];          // 8 MB

// ---------------------------------------------------------------------------
// Small helpers
// ---------------------------------------------------------------------------
__device__ __forceinline__ float sigmoidf_fast(float x) {
    return __fdividef(1.f, 1.f + __expf(-x));
}
__device__ __forceinline__ unsigned smem_to_u32(const void* p) {
    unsigned a;
    asm("{ .reg .u64 t; cvta.to.shared.u64 t, %1; cvt.u32.u64 %0, t; }"
        : "=r"(a) : "l"(p));
    return a;
}
__device__ __forceinline__ void flag_store_release(unsigned* p, unsigned v) {
    asm volatile("st.release.gpu.global.u32 [%0], %1;"
                 :: "l"(p), "r"(v) : "memory");
}
__device__ __forceinline__ unsigned flag_load_acquire(const unsigned* p) {
    unsigned v;
    asm volatile("ld.acquire.gpu.global.u32 %0, [%1];"
                 : "=r"(v) : "l"(p) : "memory");
    return v;
}
__device__ __forceinline__ void prefetch_l2(const void* p) {
    asm volatile("prefetch.global.L2 [%0];" :: "l"(p));
}

// ---------------------------------------------------------------------------
// sm_80+ portable async-copy + ldmatrix + HMMA (fp16, fp32 accumulate)
// ---------------------------------------------------------------------------
__device__ __forceinline__ void cp_async16(unsigned smem_addr, const void* gptr) {
    asm volatile("cp.async.cg.shared.global [%0], [%1], 16;"
                 :: "r"(smem_addr), "l"(gptr));
}
#define CP_COMMIT() asm volatile("cp.async.commit_group;" ::: "memory")
#define CP_WAIT(n)  asm volatile("cp.async.wait_group %0;" :: "n"(n) : "memory")

__device__ __forceinline__ void ldmatrix_x4(unsigned* r, unsigned addr) {
    asm volatile("ldmatrix.sync.aligned.m8n8.x4.shared.b16 {%0,%1,%2,%3}, [%4];"
                 : "=r"(r[0]), "=r"(r[1]), "=r"(r[2]), "=r"(r[3]) : "r"(addr));
}
__device__ __forceinline__ void mma_f16(float* c, const unsigned* a,
                                        const unsigned* b) {
    asm volatile(
        "mma.sync.aligned.m16n8k16.row.col.f32.f16.f16.f32 "
        "{%0,%1,%2,%3}, {%4,%5,%6,%7}, {%8,%9}, {%0,%1,%2,%3};"
        : "+f"(c[0]), "+f"(c[1]), "+f"(c[2]), "+f"(c[3])
        : "r"(a[0]), "r"(a[1]), "r"(a[2]), "r"(a[3]), "r"(b[0]), "r"(b[1]));
}

// ---------------------------------------------------------------------------
// Zero the cell state + step flags + fp16 emb conversion
// ---------------------------------------------------------------------------
__global__ void init_state_kernel(const float* __restrict__ emb) {
    int i = blockIdx.x * blockDim.x + threadIdx.x;
    if (i < Bq * Hq) { g_c[0][i] = 0.f; g_c[1][i] = 0.f; }
    if (i < 128) g_flags[i >> 5][i & 31] = 0u;
    if (i < Vq * Eq) g_emb16[i] = __float2half(emb[i]);
}

// ---------------------------------------------------------------------------
// Gate-interleave biases:  bt[j*4+g] = b[g*H+j]
// ---------------------------------------------------------------------------
__global__ void interleave_b_kernel(const float* __restrict__ bf,
                                    const float* __restrict__ bb) {
    int idx = blockIdx.x * blockDim.x + threadIdx.x;
    if (idx < G4H) {
        int src = (idx & 3) * Hq + (idx >> 2);
        g_btf[idx] = bf[src];
        g_btb[idx] = bb[src];
    }
}

// ---------------------------------------------------------------------------
// fp16 + transpose + gate-interleave W:  Wt16[dir][(j*4+g)][e] = fp16(W[e][g*H+j])
// ---------------------------------------------------------------------------
__global__ void transpose_W16_kernel(const float* __restrict__ Wf,
                                     const float* __restrict__ Wb) {
    __shared__ float ts[32][33];
    int j0 = blockIdx.x * 32;
    int e0 = blockIdx.y * 32;
    int g   = blockIdx.z & 3;
    int dir = blockIdx.z >> 2;
    const float* W = dir ? Wb : Wf;
    __half* D = dir ? g_Wt16b : g_Wt16f;
    int tx = threadIdx.x, ty = threadIdx.y;
#pragma unroll
    for (int i = 0; i < 32; i += 8)
        ts[ty + i][tx] = W[(size_t)(e0 + ty + i) * G4H + g * Hq + j0 + tx];
    __syncthreads();
#pragma unroll
    for (int i = 0; i < 32; i += 8) {
        int j = j0 + ty + i;
        float v = ts[tx][ty + i];
        size_t o = (size_t)((j << 2) + g) * Eq + e0 + tx;
        D[o] = __float2half(v);
    }
}

// ---------------------------------------------------------------------------
// fp16 + transpose + gate-interleave U
// ---------------------------------------------------------------------------
__global__ void split_transpose_U_kernel(const float* __restrict__ Uf,
                                         const float* __restrict__ Ub) {
    __shared__ float ts[32][33];
    int j0 = blockIdx.x * 32;
    int k0 = blockIdx.y * 32;
    int g   = blockIdx.z & 3;
    int dir = blockIdx.z >> 2;
    const float* U = dir ? Ub : Uf;
    __half* Dhi = dir ? g_Uhib : g_Uhif;
    int tx = threadIdx.x, ty = threadIdx.y;
#pragma unroll
    for (int i = 0; i < 32; i += 8)
        ts[ty + i][tx] = U[(size_t)(k0 + ty + i) * G4H + g * Hq + j0 + tx];
    __syncthreads();
#pragma unroll
    for (int i = 0; i < 32; i += 8) {
        int j = j0 + ty + i;
        float v = ts[tx][ty + i];
        size_t o = (size_t)((j << 2) + g) * Hq + k0 + tx;
        Dhi[o] = __float2half(v);
    }
}

// ---------------------------------------------------------------------------
// fp16 + transpose Wd:  Bhi[n][k] = fp16(Wd[k][n])
// ---------------------------------------------------------------------------
__global__ void split_transpose_Wd_kernel(const float* __restrict__ Wd) {
    __shared__ float ts[32][33];
    int n0 = blockIdx.x * 32;
    int k0 = blockIdx.y * 32;
    int tx = threadIdx.x, ty = threadIdx.y;
#pragma unroll
    for (int i = 0; i < 32; i += 8)
        ts[ty + i][tx] = Wd[(size_t)(k0 + ty + i) * Vq + n0 + tx];
    __syncthreads();
#pragma unroll
    for (int i = 0; i < 32; i += 8) {
        float v = ts[tx][ty + i];
        size_t o = (size_t)(n0 + ty + i) * Kout + k0 + tx;
        g_Bhi[o] = __float2half(v);
    }
}

// ---------------------------------------------------------------------------
// Generic fp16 HMMA GEMM with fp32 bias + fp32 output (unchanged, validated)
// ---------------------------------------------------------------------------
#define OG_BK       64
#define OG_RS       144
#define OG_TILE_B   (128 * OG_RS)
#define OG_STAGE_B  (2 * OG_TILE_B)
#define OG_SMEM     (2 * OG_STAGE_B)    // 73728

__global__ __launch_bounds__(256, 2) void hgemm_bias_kernel(
    const __half* __restrict__ A, const __half* __restrict__ B,
    const float* __restrict__ bias, float* __restrict__ out,
    int K, int ldout)
{
    extern __shared__ char smem[];
    const unsigned sb = smem_to_u32(smem);
    const int tid = threadIdx.x;
    const int wid = tid >> 5;
    const int lane = tid & 31;
    const int warp_m = wid >> 2;
    const int warp_n = wid & 3;
    const int n0 = blockIdx.x * 128;
    const int m0 = blockIdx.y * 128;
    const int chunks = K >> 6;

    const __half* srcs[2] = {A, B};
    const int rowbase[2] = {m0, n0};

    auto issue_chunk = [&](int kc, int buf) {
        const unsigned bb = sb + buf * OG_STAGE_B;
#pragma unroll
        for (int i = 0; i < 8; i++) {
            int id   = i * 256 + tid;
            int tile = id >> 10;
            int rem  = id & 1023;
            int r    = rem >> 3;
            int ch   = rem & 7;
            unsigned dst = bb + tile * OG_TILE_B + r * OG_RS + ch * 16;
            const void* g = srcs[tile] +
                            (size_t)(rowbase[tile] + r) * K + kc + ch * 8;
            cp_async16(dst, g);
        }
        CP_COMMIT();
    };

    float acc[4][4][4];
#pragma unroll
    for (int mt = 0; mt < 4; mt++)
#pragma unroll
        for (int nt = 0; nt < 4; nt++)
#pragma unroll
            for (int q = 0; q < 4; q++) acc[mt][nt][q] = 0.f;

    issue_chunk(0, 0);
    issue_chunk(OG_BK, 1);

    for (int c = 0; c < chunks; c++) {
        if (c < chunks - 1) { CP_WAIT(1); } else { CP_WAIT(0); }
        __syncthreads();

        const unsigned bb  = sb + (c & 1) * OG_STAGE_B;
        const unsigned sAh = bb;
        const unsigned sBh = bb + OG_TILE_B;

#pragma unroll
        for (int kh = 0; kh < 4; kh++) {
            const int koff = kh * 32;
            const unsigned a_off =
                (warp_m * 64 + (lane & 15)) * OG_RS + koff + ((lane >> 4) << 4);
            const unsigned b_off =
                (warp_n * 32 + (lane & 7) + ((lane >> 4) << 3)) * OG_RS +
                koff + (((lane >> 3) & 1) << 4);

            unsigned aH[4][4], bH[4][2];
#pragma unroll
            for (int mt = 0; mt < 4; mt++)
                ldmatrix_x4(aH[mt], sAh + a_off + mt * 16 * OG_RS);
#pragma unroll
            for (int np = 0; np < 2; np++) {
                unsigned r4[4];
                ldmatrix_x4(r4, sBh + b_off + np * 16 * OG_RS);
                bH[np * 2][0] = r4[0]; bH[np * 2][1] = r4[1];
                bH[np * 2 + 1][0] = r4[2]; bH[np * 2 + 1][1] = r4[3];
            }

#pragma unroll
            for (int mt = 0; mt < 4; mt++)
#pragma unroll
                for (int nt = 0; nt < 4; nt++)
                    mma_f16(acc[mt][nt], aH[mt], bH[nt]);
        }

        __syncthreads();
        if (c + 2 < chunks) issue_chunk((c + 2) * OG_BK, c & 1);
    }

#pragma unroll
    for (int mt = 0; mt < 4; mt++) {
        int r0 = m0 + warp_m * 64 + mt * 16 + (lane >> 2);
#pragma unroll
        for (int nt = 0; nt < 4; nt++) {
            int col = n0 + warp_n * 32 + nt * 8 + 2 * (lane & 3);
            float b0v = bias[col], b1v = bias[col + 1];
            float2 v0 = make_float2(acc[mt][nt][0] + b0v, acc[mt][nt][1] + b1v);
            float2 v1 = make_float2(acc[mt][nt][2] + b0v, acc[mt][nt][3] + b1v);
            *reinterpret_cast<float2*>(out + (size_t)r0 * ldout + col) = v0;
            *reinterpret_cast<float2*>(out + (size_t)(r0 + 8) * ldout + col) = v1;
        }
    }
}

// ---------------------------------------------------------------------------
// PERSISTENT recurrence with RESIDENT U-HALF (structure = R15, validated).
// New in R16: parallel-flag group barrier (no same-address atomic chain) and
// L2 prefetch of this step's embW gather lines before the GEMM.
// ---------------------------------------------------------------------------
#define LP_RS     256                      // bytes per 128-fp16 row (swizzled)
#define LP_UCH    (128 * LP_RS)            // 32768: U chunk (128 rows)
#define LP_ACH    (64 * LP_RS)             // 16384: A chunk (64 rows)
#define LP_STAGE  (LP_UCH + LP_ACH)        // 49152: [U][A]
#define LP_UPOFF  (2 * LP_STAGE)           // 98304
#define LP_SMEM   (LP_UPOFF + 4 * LP_UCH)  // 229376

__global__ __launch_bounds__(512, 1) void lstm_persistent_kernel(
    const int* __restrict__ tokens)
{
    extern __shared__ char smem[];
    const unsigned sb = smem_to_u32(smem);
    float (*zs)[132] = reinterpret_cast<float (*)[132]>(smem);  // 64x132 fp32
    __shared__ int toks[64];

    const int tid = threadIdx.x;
    const int wid = tid >> 5;
    const int lane = tid & 31;
    const int warp_m = wid >> 2;        // 0..3 (16 rows each)
    const int warp_n = wid & 3;         // 0..3 (32 cols each)
    const int c0  = blockIdx.x * 128;   // interleaved col base
    const int b0  = blockIdx.y * 64;
    const int dir = blockIdx.z;
    const int gid = blockIdx.y * 2 + blockIdx.z;

    const __half* Uhi = dir ? g_Uhib : g_Uhif;
    const float* embW = dir ? g_embWtb : g_embWtf;
    float* cptr = &g_c[dir][0];
    const int j0q = c0 >> 2;

    // U chunk loader (swizzled): 128 rows x 16 chunks of 16B
    auto issue_U = [&](int kc, unsigned ubase) {
#pragma unroll
        for (int i = 0; i < 4; i++) {
            int id = i * 512 + tid;            // 0..2047
            int r = id >> 4, ch = id & 15;
            unsigned dst = ubase + r * LP_RS + ((unsigned)(ch ^ (r & 7)) << 4);
            cp_async16(dst, Uhi + (size_t)(c0 + r) * Hq + kc + ch * 8);
        }
    };

    // Preload resident U chunks 0-3 (once)
    issue_U(0,   sb + LP_UPOFF);
    issue_U(128, sb + LP_UPOFF + LP_UCH);
    issue_U(256, sb + LP_UPOFF + 2 * LP_UCH);
    issue_U(384, sb + LP_UPOFF + 3 * LP_UCH);
    CP_COMMIT();
    CP_WAIT(0);
    __syncthreads();

    for (int t = 0; t < Sq; t++) {
        const int s  = dir ? (Sq - 1 - t) : t;
        const int sp = dir ? (Sq - t) : (t - 1);   // previous step's s (t>0)

        if (tid < 64) toks[tid] = tokens[(b0 + tid) * Sq + s];

        // Prefetch this step's embW gather lines into L2 (gathers happen in
        // the epilogue ~9us from now; by then they're L2-hot).
#pragma unroll
        for (int it = 0; it < 4; it++) {
            int idx = it * 512 + tid;
            int r  = idx >> 5;
            int jj = idx & 31;
            int tok = tokens[(b0 + r) * Sq + s];          // warp-broadcast LDG
            prefetch_l2(&embW[(size_t)tok * G4H + ((j0q + jj) << 2)]);
        }

        float acc[4][4];                    // [nt][quad]
#pragma unroll
        for (int nt = 0; nt < 4; nt++)
#pragma unroll
            for (int q = 0; q < 4; q++) acc[nt][q] = 0.f;

        if (t > 0) {
            auto issue_A = [&](int c, int buf) {
#pragma unroll
                for (int i = 0; i < 2; i++) {
                    int id = i * 512 + tid;        // 0..1023
                    int r = id >> 4, ch = id & 15;
                    unsigned dst = sb + buf * LP_STAGE + LP_UCH +
                                   r * LP_RS + ((unsigned)(ch ^ (r & 7)) << 4);
                    cp_async16(dst, g_Ahi +
                        ((size_t)(b0 + r) * Sq + sp) * Kout + dir * Hq +
                        c * 128 + ch * 8);
                }
            };

            // G0 = A0;  G1 = A1 + U4(stream->buf0.U)
            issue_A(0, 0); CP_COMMIT();
            issue_A(1, 1); issue_U(512, sb); CP_COMMIT();

            for (int c = 0; c < 8; c++) {
                if (c < 7) { CP_WAIT(1); } else { CP_WAIT(0); }
                __syncthreads();

                const unsigned Bbase = (c < 4)
                    ? (sb + LP_UPOFF + c * LP_UCH)
                    : (sb + (c & 1) * LP_STAGE);
                const unsigned Abase = sb + (c & 1) * LP_STAGE + LP_UCH;

#pragma unroll
                for (int kh = 0; kh < 8; kh++) {
                    const int a_row = warp_m * 16 + (lane & 15);
                    const int a_c16 = kh * 2 + (lane >> 4);
                    unsigned aH[4];
                    ldmatrix_x4(aH, Abase + a_row * LP_RS +
                                ((unsigned)((a_c16 ^ (a_row & 7))) << 4));

                    unsigned bH[4][2];
#pragma unroll
                    for (int np = 0; np < 2; np++) {
                        const int b_row = warp_n * 32 + (lane & 7) +
                                          ((lane >> 4) << 3) + np * 16;
                        const int b_c16 = kh * 2 + ((lane >> 3) & 1);
                        unsigned r4[4];
                        ldmatrix_x4(r4, Bbase + b_row * LP_RS +
                                    ((unsigned)((b_c16 ^ (b_row & 7))) << 4));
                        bH[np * 2][0] = r4[0]; bH[np * 2][1] = r4[1];
                        bH[np * 2 + 1][0] = r4[2]; bH[np * 2 + 1][1] = r4[3];
                    }

#pragma unroll
                    for (int nt = 0; nt < 4; nt++)
                        mma_f16(acc[nt], aH, bH[nt]);
                }

                __syncthreads();

                // Post-issue schedule (verified clobber/order-safe):
                if      (c == 0) { issue_A(2, 0); issue_U(640, sb + LP_STAGE); CP_COMMIT(); }
                else if (c == 1) { issue_A(3, 1); CP_COMMIT(); }
                else if (c == 2) { issue_A(4, 0); CP_COMMIT(); }
                else if (c == 3) { issue_A(5, 1); CP_COMMIT(); }
                else if (c == 4) { issue_A(6, 0); issue_U(768, sb); CP_COMMIT(); }
                else if (c == 5) { issue_A(7, 1); issue_U(896, sb + LP_STAGE); CP_COMMIT(); }
            }
        }

        __syncthreads();   // all MMA reads done; safe to alias buf0 as zs

        // fragments -> z tile
        {
            int r = warp_m * 16 + (lane >> 2);
#pragma unroll
            for (int nt = 0; nt < 4; nt++) {
                int col = warp_n * 32 + nt * 8 + 2 * (lane & 3);
                *reinterpret_cast<float2*>(&zs[r][col]) =
                    make_float2(acc[nt][0], acc[nt][1]);
                *reinterpret_cast<float2*>(&zs[r + 8][col]) =
                    make_float2(acc[nt][2], acc[nt][3]);
            }
        }
        __syncthreads();

        // fused gate update: 64 rows x 32 hidden units / 512 threads
#pragma unroll
        for (int it = 0; it < 4; it++) {
            int idx = it * 512 + tid;
            int r  = idx >> 5;     // 0..63
            int jj = idx & 31;     // 0..31
            int j = j0q + jj;

            float4 z4 = *reinterpret_cast<const float4*>(&zs[r][jj * 4]);
            int tok = toks[r];
            float4 ew = *reinterpret_cast<const float4*>(
                &embW[(size_t)tok * G4H + (j << 2)]);
            float zi = z4.x + ew.x;
            float zf = z4.y + ew.y;
            float zg = z4.z + ew.z;
            float zo = z4.w + ew.w;

            float ig = sigmoidf_fast(zi);
            float fg = sigmoidf_fast(zf);
            float og = sigmoidf_fast(zo);
            float gg = dir ? fmaxf(zg, 0.f) : tanhf(zg);

            int ci = (b0 + r) * Hq + j;
            float cv = fg * cptr[ci] + ig * gg;
            cptr[ci] = cv;
            float hc = dir ? fmaxf(cv, 0.f) : tanhf(cv);
            float hv = og * hc;

            size_t ao = ((size_t)(b0 + r) * Sq + s) * Kout + dir * Hq + j;
            g_Ahi[ao] = __float2half(hv);
        }

        // ---- 32-CTA group barrier: per-CTA flag + parallel poll ----
        if (t + 1 < Sq) {
            __syncthreads();               // all epilogue STGs issued
            if (tid == 0)
                flag_store_release(&g_flags[gid][blockIdx.x], (unsigned)(t + 1));
            if (wid == 0) {
                const unsigned tgt = (unsigned)(t + 1);
                const unsigned* fp = &g_flags[gid][lane];
                unsigned v;
                do { v = flag_load_acquire(fp); }
                while (!__all_sync(0xFFFFFFFFu, v >= tgt));
            }
            __syncthreads();               // broadcast completion to all warps
        }
    }
}

// ---------------------------------------------------------------------------
// Launch
// ---------------------------------------------------------------------------
extern "C" void kernel_launch(void* const* d_in, const int* in_sizes, int n_in,
                              void* d_out, int out_size) {
    (void)in_sizes; (void)n_in; (void)out_size;
    const int*   tokens = (const int*)  d_in[0];
    const float* emb    = (const float*)d_in[1];
    const float* Wf     = (const float*)d_in[2];
    const float* Uf     = (const float*)d_in[3];
    const float* bf     = (const float*)d_in[4];
    const float* Wb     = (const float*)d_in[5];
    const float* Ub     = (const float*)d_in[6];
    const float* bb     = (const float*)d_in[7];
    const float* Wd     = (const float*)d_in[8];
    const float* bd     = (const float*)d_in[9];
    float* out = (float*)d_out;

    float *p_btf, *p_btb, *p_embWtf, *p_embWtb;
    __half *p_emb16, *p_Wt16f, *p_Wt16b, *p_Ahi, *p_Bhi;
    cudaGetSymbolAddress((void**)&p_btf,    g_btf);
    cudaGetSymbolAddress((void**)&p_btb,    g_btb);
    cudaGetSymbolAddress((void**)&p_embWtf, g_embWtf);
    cudaGetSymbolAddress((void**)&p_embWtb, g_embWtb);
    cudaGetSymbolAddress((void**)&p_emb16,  g_emb16);
    cudaGetSymbolAddress((void**)&p_Wt16f,  g_Wt16f);
    cudaGetSymbolAddress((void**)&p_Wt16b,  g_Wt16b);
    cudaGetSymbolAddress((void**)&p_Ahi,    g_Ahi);
    cudaGetSymbolAddress((void**)&p_Bhi,    g_Bhi);

    cudaFuncSetAttribute(hgemm_bias_kernel,
                         cudaFuncAttributeMaxDynamicSharedMemorySize, OG_SMEM);
    cudaFuncSetAttribute(lstm_persistent_kernel,
                         cudaFuncAttributeMaxDynamicSharedMemorySize, LP_SMEM);

    init_state_kernel<<<(Vq * Eq + 255) / 256, 256>>>(emb);
    interleave_b_kernel<<<(G4H + 255) / 256, 256>>>(bf, bb);
    transpose_W16_kernel<<<dim3(Hq / 32, Eq / 32, 8), dim3(32, 8)>>>(Wf, Wb);
    split_transpose_U_kernel<<<dim3(Hq / 32, Hq / 32, 8), dim3(32, 8)>>>(Uf, Ub);
    split_transpose_Wd_kernel<<<dim3(Vq / 32, Kout / 32), dim3(32, 8)>>>(Wd);

    // embWt = emb16 @ Wt16^T + bt  (gate-interleaved, bias folded), fp16 HMMA
    hgemm_bias_kernel<<<dim3(G4H / 128, Vq / 128), 256, OG_SMEM>>>(
        p_emb16, p_Wt16f, p_btf, p_embWtf, Eq, G4H);
    hgemm_bias_kernel<<<dim3(G4H / 128, Vq / 128), 256, OG_SMEM>>>(
        p_emb16, p_Wt16b, p_btb, p_embWtb, Eq, G4H);

    // ALL 256 recurrent steps in one persistent launch
    lstm_persistent_kernel<<<dim3(G4H / 128, Bq / 64, 2), 512, LP_SMEM>>>(tokens);

    // out = hcat16 @ Wd16^T + bd
    hgemm_bias_kernel<<<dim3(Vq / 128, Mout / 128), 256, OG_SMEM>>>(
        p_Ahi, p_Bhi, bd, out, Kout, Vq);
}